// round 15
// baseline (speedup 1.0000x reference)
#include <cuda_runtime.h>
#include <cstdint>
#include <cstddef>

#define THREADS 256
#define TILE_ROWS 32
#define STRIDE 132                               // floats; 528B rows
#define TILE_SMEM_FLOATS (TILE_ROWS * STRIDE)
#define TILE_SMEM_BYTES (TILE_SMEM_FLOATS * 4)   // 16896
#define NSTAGE 2
#define NTILES 16384                             // 8*256*256 / 32

__device__ float g_R2[8 * 256 * 128];     // Vx + 0.5*Ub  (1 MB)
__device__ float4 g_Q01[4 * 16 * 32];     // streamed B pairs oc0,1 (32 KB)
__device__ float4 g_Q23[4 * 16 * 32];     // streamed B pairs oc2,3 (32 KB)

__device__ __forceinline__ uint32_t f2tf32(float f) {
    uint32_t r;
    asm("cvt.rna.tf32.f32 %0, %1;" : "=r"(r) : "f"(f));
    return r;
}
__device__ __forceinline__ uint32_t smem_u32(const void* p) {
    uint32_t a;
    asm("{ .reg .u64 t; cvta.to.shared.u64 t, %1; cvt.u32.u64 %0, t; }" : "=r"(a) : "l"(p));
    return a;
}

// Stage one 32x128 fp32 tile into SMEM via cp.async.cg; ALWAYS commits a group.
__device__ __forceinline__ void stage_cp(uint32_t sdst, const float* __restrict__ src,
                                         int tid, bool pred) {
    if (pred) {
#pragma unroll
        for (int q = 0; q < 4; q++) {
            int idx = tid + q * THREADS;                   // 0..1023 x 16B
            uint32_t dst = sdst + (uint32_t)((idx >> 5) * (STRIDE * 4) + (idx & 31) * 16);
            asm volatile("cp.async.cg.shared.global [%0], [%1], 16;"
                         :: "r"(dst), "l"(src + (size_t)idx * 4) : "memory");
        }
    }
    asm volatile("cp.async.commit_group;" ::: "memory");
}

// ---------------------------------------------------------------------------
// Fused prep kernel (round-12). Blocks [0,128): Vx. Blocks [128,144): pack.
// Pack permutation: o = nc*32 + 8*(g>>1) + 2*oc + (g&1); thread (g,tg) then
// owns o-range [nc*32 + 8*tg, +8) contiguously in the epilogue.
// ---------------------------------------------------------------------------
__global__ __launch_bounds__(256) void prep_kernel(
    const float* __restrict__ x,  const float* __restrict__ Vw,
    const float* __restrict__ Vb, const float* __restrict__ Ub,
    const float* __restrict__ Uw)
{
    if (blockIdx.x >= 128) {                     // ---- pack part ----
        int p = (blockIdx.x - 128) * 256 + threadIdx.x;   // 0..4095
        int r    = p & 2047;
        int lane = r & 31, ks = (r >> 5) & 15, nc = r >> 9;
        int g    = lane >> 2;
        int k0   = ks * 8 + (lane & 3);
        int base = nc * 32 + 8 * (g >> 1) + (g & 1);
        if (p < 2048) {                          // oc 0,1
            int row0 = base + 0, row1 = base + 2;
            g_Q01[r] = make_float4(
                __uint_as_float(f2tf32(Uw[row0 * 128 + k0])),
                __uint_as_float(f2tf32(Uw[row0 * 128 + k0 + 4])),
                __uint_as_float(f2tf32(Uw[row1 * 128 + k0])),
                __uint_as_float(f2tf32(Uw[row1 * 128 + k0 + 4])));
        } else {                                 // oc 2,3
            int row2 = base + 4, row3 = base + 6;
            g_Q23[r] = make_float4(
                __uint_as_float(f2tf32(Uw[row2 * 128 + k0])),
                __uint_as_float(f2tf32(Uw[row2 * 128 + k0 + 4])),
                __uint_as_float(f2tf32(Uw[row3 * 128 + k0])),
                __uint_as_float(f2tf32(Uw[row3 * 128 + k0 + 4])));
        }
        return;
    }
    // ---- Vx part ----
    __shared__ float xs[16 * 128];
    int tid = threadIdx.x;
    int rbase = blockIdx.x * 16;
    const float4* xp = reinterpret_cast<const float4*>(x + rbase * 128);
    float4* xsp = reinterpret_cast<float4*>(xs);
#pragma unroll
    for (int q = 0; q < 2; q++) xsp[tid + q * 256] = xp[tid + q * 256];
    __syncthreads();

    int o  = tid & 127;
    int r0 = tid >> 7;
    float acc[8];
    float bias = Vb[o] + 0.5f * Ub[o];
#pragma unroll
    for (int k = 0; k < 8; k++) acc[k] = bias;
    const float4* wr = reinterpret_cast<const float4*>(Vw + o * 128);
#pragma unroll
    for (int h4 = 0; h4 < 32; h4++) {
        float4 w = wr[h4];
#pragma unroll
        for (int k = 0; k < 8; k++) {
            const float* xr = xs + (r0 + 2 * k) * 128 + h4 * 4;
            acc[k] += w.x * xr[0] + w.y * xr[1] + w.z * xr[2] + w.w * xr[3];
        }
    }
#pragma unroll
    for (int k = 0; k < 8; k++)
        g_R2[(rbase + r0 + 2 * k) * 128 + o] = acc[k];
}

// ---------------------------------------------------------------------------
// Edge kernel: round-12 per-warp structure at 3 CTAs/SM (24 warps).
// 256 threads, 8 warps = 2 row-groups (16 rows each) x 4 n-chunks over a
// 32-row tile. Manual ks pipeline; B streamed from L1-resident tables.
//   out[m,o] = e[m,:].Uw[o,:] + R2[b,i,o] + R2[b,j,o]
// ---------------------------------------------------------------------------
__global__ __launch_bounds__(THREADS, 3) void edge_kernel(
    const float* __restrict__ e, float* __restrict__ out)
{
    extern __shared__ float smem[];
    const int tid  = threadIdx.x;
    const int lane = tid & 31;
    const int warp = tid >> 5;
    const int rg   = warp >> 2;              // row group 0/1 (16 rows each)
    const int nc   = warp & 3;               // n chunk
    const int g    = lane >> 2;
    const int tg   = lane & 3;
    const int ob8  = nc * 32 + 8 * tg;       // thread's contiguous o-range start
    uint32_t sbase = smem_u32(smem);

    // ldmatrix per-lane byte offset within the warp's 16-row group
    const uint32_t lmoff = (uint32_t)(
        (rg * 16 + (((lane >> 3) & 1) * 8 + (lane & 7))) * STRIDE * 4
        + (lane >> 4) * 16);

    const float4* Q01p = g_Q01 + (size_t)(nc * 16) * 32 + lane;
    const float4* Q23p = g_Q23 + (size_t)(nc * 16) * 32 + lane;

    const int G  = (int)gridDim.x;
    const int t0 = (int)blockIdx.x;
    stage_cp(sbase, e + (size_t)t0 * (TILE_ROWS * 128), tid, t0 < NTILES);

    int s = 0;
    for (int t = t0; t < NTILES; t += G, s++) {
        const int buf = s & 1;
        const int base_m = t * TILE_ROWS;
        const int b  = base_m >> 16;
        const int i  = (base_m >> 8) & 255;
        const int j0 = base_m & 255;

        // ---- Prefetch row-bias Ri (8 regs); Rj handled in epilogue ----
        float4 si0, si1;
        {
            const float* Ri = g_R2 + ((size_t)(b * 256 + i) * 128 + ob8);
            si0 = *reinterpret_cast<const float4*>(Ri);
            si1 = *reinterpret_cast<const float4*>(Ri + 4);
        }

        asm volatile("cp.async.wait_group 0;" ::: "memory");
        __syncthreads();                         // tile buf ready; buf^1 free
        {
            const int tn = t + G;
            stage_cp(sbase + (uint32_t)((buf ^ 1) * TILE_SMEM_BYTES),
                     e + (size_t)tn * (TILE_ROWS * 128), tid, tn < NTILES);
        }

        const uint32_t abase = sbase + (uint32_t)(buf * TILE_SMEM_BYTES) + lmoff;
        float c[4][4];
#pragma unroll
        for (int oc = 0; oc < 4; oc++)
#pragma unroll
            for (int q = 0; q < 4; q++) c[oc][q] = 0.f;

        // ---- Manually double-buffered ks pipeline ----
        uint32_t A[2][4];
        uint32_t Bq[2][8];
        {
            float4 b01 = Q01p[0], b23 = Q23p[0];
            Bq[0][0] = __float_as_uint(b01.x); Bq[0][1] = __float_as_uint(b01.y);
            Bq[0][2] = __float_as_uint(b01.z); Bq[0][3] = __float_as_uint(b01.w);
            Bq[0][4] = __float_as_uint(b23.x); Bq[0][5] = __float_as_uint(b23.y);
            Bq[0][6] = __float_as_uint(b23.z); Bq[0][7] = __float_as_uint(b23.w);
            asm volatile(
                "ldmatrix.sync.aligned.m8n8.x4.shared.b16 {%0,%1,%2,%3}, [%4];"
                : "=r"(A[0][0]), "=r"(A[0][1]), "=r"(A[0][2]), "=r"(A[0][3])
                : "r"(abase));
        }
#pragma unroll
        for (int ks = 0; ks < 16; ks++) {
            const int cur = ks & 1;
            if (ks < 15) {
                const int nxt = cur ^ 1;
                float4 b01 = Q01p[(ks + 1) * 32], b23 = Q23p[(ks + 1) * 32];
                Bq[nxt][0] = __float_as_uint(b01.x); Bq[nxt][1] = __float_as_uint(b01.y);
                Bq[nxt][2] = __float_as_uint(b01.z); Bq[nxt][3] = __float_as_uint(b01.w);
                Bq[nxt][4] = __float_as_uint(b23.x); Bq[nxt][5] = __float_as_uint(b23.y);
                Bq[nxt][6] = __float_as_uint(b23.z); Bq[nxt][7] = __float_as_uint(b23.w);
                asm volatile(
                    "ldmatrix.sync.aligned.m8n8.x4.shared.b16 {%0,%1,%2,%3}, [%4];"
                    : "=r"(A[nxt][0]), "=r"(A[nxt][1]),
                      "=r"(A[nxt][2]), "=r"(A[nxt][3])
                    : "r"(abase + (uint32_t)((ks + 1) * 32)));
            }
#pragma unroll
            for (int oc = 0; oc < 4; oc++)
                asm volatile(
                    "mma.sync.aligned.m16n8k8.row.col.f32.tf32.tf32.f32 "
                    "{%0,%1,%2,%3}, {%4,%5,%6,%7}, {%8,%9}, {%0,%1,%2,%3};"
                    : "+f"(c[oc][0]), "+f"(c[oc][1]), "+f"(c[oc][2]), "+f"(c[oc][3])
                    : "r"(A[cur][0]), "r"(A[cur][1]), "r"(A[cur][2]), "r"(A[cur][3]),
                      "r"(Bq[cur][oc * 2]), "r"(Bq[cur][oc * 2 + 1]));
        }

        // ---- Epilogue: rows rg*16+g and +8; streaming stores ----
        const float* Rbase = g_R2 + ((size_t)(b * 256 + j0) * 128 + ob8);
#pragma unroll
        for (int q = 0; q < 2; q++) {
            const int h2 = q * 2;
            const int row = rg * 16 + q * 8 + g;
            float4 R0 = *reinterpret_cast<const float4*>(Rbase + (size_t)row * 128);
            float4 R1 = *reinterpret_cast<const float4*>(Rbase + (size_t)row * 128 + 4);
            float4 v0 = make_float4(c[0][h2]     + si0.x + R0.x,
                                    c[0][h2 + 1] + si0.y + R0.y,
                                    c[1][h2]     + si0.z + R0.z,
                                    c[1][h2 + 1] + si0.w + R0.w);
            float4 v1 = make_float4(c[2][h2]     + si1.x + R1.x,
                                    c[2][h2 + 1] + si1.y + R1.y,
                                    c[3][h2]     + si1.z + R1.z,
                                    c[3][h2 + 1] + si1.w + R1.w);
            float* op = out + ((size_t)(base_m + row) * 128 + ob8);
            __stcs(reinterpret_cast<float4*>(op),     v0);
            __stcs(reinterpret_cast<float4*>(op + 4), v1);
        }
    }
}

// ---------------------------------------------------------------------------
// Inputs (metadata order): x, e, U_w, U_b, V_w, V_b. Output fp32 [8,256,256,128].
// ---------------------------------------------------------------------------
extern "C" void kernel_launch(void* const* d_in, const int* in_sizes, int n_in,
                              void* d_out, int out_size) {
    const float* x  = (const float*)d_in[0];
    const float* e  = (const float*)d_in[1];
    const float* Uw = (const float*)d_in[2];
    const float* Ub = (const float*)d_in[3];
    const float* Vw = (const float*)d_in[4];
    const float* Vb = (const float*)d_in[5];
    float* out = (float*)d_out;

    cudaFuncSetAttribute(edge_kernel, cudaFuncAttributeMaxDynamicSharedMemorySize,
                         NSTAGE * TILE_SMEM_BYTES);

    int nsm = 148;
    cudaDeviceGetAttribute(&nsm, cudaDevAttrMultiProcessorCount, 0);

    prep_kernel<<<144, 256>>>(x, Vw, Vb, Ub, Uw);
    edge_kernel<<<3 * nsm, THREADS, NSTAGE * TILE_SMEM_BYTES>>>(e, out);
}

// round 16
// speedup vs baseline: 1.1510x; 1.1510x over previous
#include <cuda_runtime.h>
#include <cstdint>
#include <cstddef>

#define THREADS 256
#define TILE_ROWS 64
#define STRIDE 132                               // floats; 528B rows
#define TILE_SMEM_FLOATS (TILE_ROWS * STRIDE)
#define TILE_SMEM_BYTES (TILE_SMEM_FLOATS * 4)   // 33792
#define NSTAGE 2
#define NTILES 8192                              // 8*256*256 / 64

__device__ float g_R2[8 * 256 * 128];     // Vx + 0.5*Ub  (1 MB)
__device__ float4 g_Q01[4 * 16 * 32];     // streamed B pairs oc0,1 (32 KB)
__device__ float4 g_Q23[4 * 16 * 32];     // streamed B pairs oc2,3 (32 KB)

__device__ __forceinline__ uint32_t f2tf32(float f) {
    uint32_t r;
    asm("cvt.rna.tf32.f32 %0, %1;" : "=r"(r) : "f"(f));
    return r;
}
__device__ __forceinline__ uint32_t smem_u32(const void* p) {
    uint32_t a;
    asm("{ .reg .u64 t; cvta.to.shared.u64 t, %1; cvt.u32.u64 %0, t; }" : "=r"(a) : "l"(p));
    return a;
}

// Stage one 64x128 fp32 tile into SMEM via cp.async.cg; ALWAYS commits a group.
__device__ __forceinline__ void stage_cp(uint32_t sdst, const float* __restrict__ src,
                                         int tid, bool pred) {
    if (pred) {
#pragma unroll
        for (int q = 0; q < 8; q++) {
            int idx = tid + q * THREADS;                   // 0..2047 x 16B
            uint32_t dst = sdst + (uint32_t)((idx >> 5) * (STRIDE * 4) + (idx & 31) * 16);
            asm volatile("cp.async.cg.shared.global [%0], [%1], 16;"
                         :: "r"(dst), "l"(src + (size_t)idx * 4) : "memory");
        }
    }
    asm volatile("cp.async.commit_group;" ::: "memory");
}

// ---------------------------------------------------------------------------
// Fused prep kernel. Blocks [0,256): Vx (8 rows each). Blocks [256,272): pack.
// Pack permutation: o = nc*32 + 8*(g>>1) + 2*oc + (g&1); thread (g,tg) then
// owns o-range [nc*32 + 8*tg, +8) contiguously in the epilogue.
// ---------------------------------------------------------------------------
__global__ __launch_bounds__(256) void prep_kernel(
    const float* __restrict__ x,  const float* __restrict__ Vw,
    const float* __restrict__ Vb, const float* __restrict__ Ub,
    const float* __restrict__ Uw)
{
    if (blockIdx.x >= 256) {                     // ---- pack part ----
        int p = (blockIdx.x - 256) * 256 + threadIdx.x;   // 0..4095
        int r    = p & 2047;
        int lane = r & 31, ks = (r >> 5) & 15, nc = r >> 9;
        int g    = lane >> 2;
        int k0   = ks * 8 + (lane & 3);
        int base = nc * 32 + 8 * (g >> 1) + (g & 1);
        if (p < 2048) {                          // oc 0,1
            int row0 = base + 0, row1 = base + 2;
            g_Q01[r] = make_float4(
                __uint_as_float(f2tf32(Uw[row0 * 128 + k0])),
                __uint_as_float(f2tf32(Uw[row0 * 128 + k0 + 4])),
                __uint_as_float(f2tf32(Uw[row1 * 128 + k0])),
                __uint_as_float(f2tf32(Uw[row1 * 128 + k0 + 4])));
        } else {                                 // oc 2,3
            int row2 = base + 4, row3 = base + 6;
            g_Q23[r] = make_float4(
                __uint_as_float(f2tf32(Uw[row2 * 128 + k0])),
                __uint_as_float(f2tf32(Uw[row2 * 128 + k0 + 4])),
                __uint_as_float(f2tf32(Uw[row3 * 128 + k0])),
                __uint_as_float(f2tf32(Uw[row3 * 128 + k0 + 4])));
        }
        return;
    }
    // ---- Vx part: 8 rows per block ----
    __shared__ float xs[8 * 128];
    int tid = threadIdx.x;
    int rbase = blockIdx.x * 8;
    reinterpret_cast<float4*>(xs)[tid] =
        reinterpret_cast<const float4*>(x + rbase * 128)[tid];
    __syncthreads();

    int o  = tid & 127;
    int r0 = tid >> 7;                           // 0/1; rows r0+2k, k<4
    float acc[4];
    float bias = Vb[o] + 0.5f * Ub[o];
#pragma unroll
    for (int k = 0; k < 4; k++) acc[k] = bias;
    const float4* wr = reinterpret_cast<const float4*>(Vw + o * 128);
#pragma unroll
    for (int h4 = 0; h4 < 32; h4++) {
        float4 w = wr[h4];
#pragma unroll
        for (int k = 0; k < 4; k++) {
            const float* xr = xs + (r0 + 2 * k) * 128 + h4 * 4;
            acc[k] += w.x * xr[0] + w.y * xr[1] + w.z * xr[2] + w.w * xr[3];
        }
    }
#pragma unroll
    for (int k = 0; k < 4; k++)
        g_R2[(rbase + r0 + 2 * k) * 128 + o] = acc[k];
}

// ---------------------------------------------------------------------------
// Edge kernel (round-12 winner, byte-identical mainloop).
// 256 threads, 8 warps = 2 row-groups x 4 n-chunks over a 64-row tile;
// all B streamed from L1-resident packed tables; manual ks pipeline.
//   out[m,o] = e[m,:].Uw[o,:] + R2[b,i,o] + R2[b,j,o]
// ---------------------------------------------------------------------------
__global__ __launch_bounds__(THREADS, 2) void edge_kernel(
    const float* __restrict__ e, float* __restrict__ out)
{
    extern __shared__ float smem[];
    const int tid  = threadIdx.x;
    const int lane = tid & 31;
    const int warp = tid >> 5;
    const int rg   = warp >> 2;              // row group 0/1
    const int nc   = warp & 3;               // n chunk
    const int g    = lane >> 2;
    const int tg   = lane & 3;
    const int ob8  = nc * 32 + 8 * tg;       // thread's contiguous o-range start
    uint32_t sbase = smem_u32(smem);

    // ldmatrix per-lane byte offset within the warp's 32-row group
    const uint32_t lmoff = (uint32_t)(
        (rg * 32 + (((lane >> 3) & 1) * 8 + (lane & 7))) * STRIDE * 4
        + (lane >> 4) * 16);

    const float4* Q01p = g_Q01 + (size_t)(nc * 16) * 32 + lane;
    const float4* Q23p = g_Q23 + (size_t)(nc * 16) * 32 + lane;

    const int G  = (int)gridDim.x;
    const int t0 = (int)blockIdx.x;
    stage_cp(sbase, e + (size_t)t0 * (TILE_ROWS * 128), tid, t0 < NTILES);

    int s = 0;
    for (int t = t0; t < NTILES; t += G, s++) {
        const int buf = s & 1;
        const int base_m = t * TILE_ROWS;
        const int b  = base_m >> 16;
        const int i  = (base_m >> 8) & 255;
        const int j0 = base_m & 255;

        // ---- Prefetch row-bias Ri only (8 regs); Rj handled in epilogue ----
        float4 si0, si1;
        {
            const float* Ri = g_R2 + ((size_t)(b * 256 + i) * 128 + ob8);
            si0 = *reinterpret_cast<const float4*>(Ri);
            si1 = *reinterpret_cast<const float4*>(Ri + 4);
        }

        asm volatile("cp.async.wait_group 0;" ::: "memory");
        __syncthreads();                         // tile buf ready; buf^1 free
        {
            const int tn = t + G;
            stage_cp(sbase + (uint32_t)((buf ^ 1) * TILE_SMEM_BYTES),
                     e + (size_t)tn * (TILE_ROWS * 128), tid, tn < NTILES);
        }

        const uint32_t abase = sbase + (uint32_t)(buf * TILE_SMEM_BYTES) + lmoff;
        float c[2][4][4];
#pragma unroll
        for (int mt = 0; mt < 2; mt++)
#pragma unroll
            for (int oc = 0; oc < 4; oc++)
#pragma unroll
                for (int q = 0; q < 4; q++) c[mt][oc][q] = 0.f;

        // ---- Manually double-buffered ks pipeline ----
        uint32_t A[2][2][4];      // [pipe buf][mt][frag]
        uint32_t Bq[2][8];        // [pipe buf][B0..B3 x2]
        {
            float4 b01 = Q01p[0], b23 = Q23p[0];
            Bq[0][0] = __float_as_uint(b01.x); Bq[0][1] = __float_as_uint(b01.y);
            Bq[0][2] = __float_as_uint(b01.z); Bq[0][3] = __float_as_uint(b01.w);
            Bq[0][4] = __float_as_uint(b23.x); Bq[0][5] = __float_as_uint(b23.y);
            Bq[0][6] = __float_as_uint(b23.z); Bq[0][7] = __float_as_uint(b23.w);
#pragma unroll
            for (int mt = 0; mt < 2; mt++)
                asm volatile(
                    "ldmatrix.sync.aligned.m8n8.x4.shared.b16 {%0,%1,%2,%3}, [%4];"
                    : "=r"(A[0][mt][0]), "=r"(A[0][mt][1]),
                      "=r"(A[0][mt][2]), "=r"(A[0][mt][3])
                    : "r"(abase + (uint32_t)(mt * 16 * STRIDE * 4)));
        }
#pragma unroll
        for (int ks = 0; ks < 16; ks++) {
            const int cur = ks & 1;
            if (ks < 15) {
                const int nxt = cur ^ 1;
                float4 b01 = Q01p[(ks + 1) * 32], b23 = Q23p[(ks + 1) * 32];
                Bq[nxt][0] = __float_as_uint(b01.x); Bq[nxt][1] = __float_as_uint(b01.y);
                Bq[nxt][2] = __float_as_uint(b01.z); Bq[nxt][3] = __float_as_uint(b01.w);
                Bq[nxt][4] = __float_as_uint(b23.x); Bq[nxt][5] = __float_as_uint(b23.y);
                Bq[nxt][6] = __float_as_uint(b23.z); Bq[nxt][7] = __float_as_uint(b23.w);
#pragma unroll
                for (int mt = 0; mt < 2; mt++)
                    asm volatile(
                        "ldmatrix.sync.aligned.m8n8.x4.shared.b16 {%0,%1,%2,%3}, [%4];"
                        : "=r"(A[nxt][mt][0]), "=r"(A[nxt][mt][1]),
                          "=r"(A[nxt][mt][2]), "=r"(A[nxt][mt][3])
                        : "r"(abase + (uint32_t)((mt * 16 * STRIDE + (ks + 1) * 8) * 4)));
            }
#pragma unroll
            for (int mt = 0; mt < 2; mt++) {
#pragma unroll
                for (int oc = 0; oc < 4; oc++)
                    asm volatile(
                        "mma.sync.aligned.m16n8k8.row.col.f32.tf32.tf32.f32 "
                        "{%0,%1,%2,%3}, {%4,%5,%6,%7}, {%8,%9}, {%0,%1,%2,%3};"
                        : "+f"(c[mt][oc][0]), "+f"(c[mt][oc][1]),
                          "+f"(c[mt][oc][2]), "+f"(c[mt][oc][3])
                        : "r"(A[cur][mt][0]), "r"(A[cur][mt][1]),
                          "r"(A[cur][mt][2]), "r"(A[cur][mt][3]),
                          "r"(Bq[cur][oc * 2]), "r"(Bq[cur][oc * 2 + 1]));
            }
        }

        // ---- Epilogue: Rj loaded here (batched, MLP-covered); streaming stores ----
        const float* Rbase = g_R2 + ((size_t)(b * 256 + j0) * 128 + ob8);
#pragma unroll
        for (int q = 0; q < 4; q++) {
            const int mt = q >> 1;
            const int h2 = (q & 1) * 2;
            const int row = rg * 32 + (q >> 1) * 16 + (q & 1) * 8 + g;
            float4 R0 = *reinterpret_cast<const float4*>(Rbase + (size_t)row * 128);
            float4 R1 = *reinterpret_cast<const float4*>(Rbase + (size_t)row * 128 + 4);
            float4 v0 = make_float4(c[mt][0][h2]     + si0.x + R0.x,
                                    c[mt][0][h2 + 1] + si0.y + R0.y,
                                    c[mt][1][h2]     + si0.z + R0.z,
                                    c[mt][1][h2 + 1] + si0.w + R0.w);
            float4 v1 = make_float4(c[mt][2][h2]     + si1.x + R1.x,
                                    c[mt][2][h2 + 1] + si1.y + R1.y,
                                    c[mt][3][h2]     + si1.z + R1.z,
                                    c[mt][3][h2 + 1] + si1.w + R1.w);
            float* op = out + ((size_t)(base_m + row) * 128 + ob8);
            __stcs(reinterpret_cast<float4*>(op),     v0);
            __stcs(reinterpret_cast<float4*>(op + 4), v1);
        }
    }
}

// ---------------------------------------------------------------------------
// Inputs (metadata order): x, e, U_w, U_b, V_w, V_b. Output fp32 [8,256,256,128].
// ---------------------------------------------------------------------------
extern "C" void kernel_launch(void* const* d_in, const int* in_sizes, int n_in,
                              void* d_out, int out_size) {
    const float* x  = (const float*)d_in[0];
    const float* e  = (const float*)d_in[1];
    const float* Uw = (const float*)d_in[2];
    const float* Ub = (const float*)d_in[3];
    const float* Vw = (const float*)d_in[4];
    const float* Vb = (const float*)d_in[5];
    float* out = (float*)d_out;

    cudaFuncSetAttribute(edge_kernel, cudaFuncAttributeMaxDynamicSharedMemorySize,
                         NSTAGE * TILE_SMEM_BYTES);

    int nsm = 148;
    cudaDeviceGetAttribute(&nsm, cudaDevAttrMultiProcessorCount, 0);

    prep_kernel<<<272, 256>>>(x, Vw, Vb, Ub, Uw);
    edge_kernel<<<2 * nsm, THREADS, NSTAGE * TILE_SMEM_BYTES>>>(e, out);
}

// round 17
// speedup vs baseline: 1.1851x; 1.0296x over previous
#include <cuda_runtime.h>
#include <cstdint>
#include <cstddef>

#define THREADS 256
#define TILE_ROWS 64
#define STRIDE 132                               // floats; 528B rows
#define TILE_SMEM_FLOATS (TILE_ROWS * STRIDE)
#define TILE_SMEM_BYTES (TILE_SMEM_FLOATS * 4)   // 33792
#define NSTAGE 2
#define NTILES 8192                              // 8*256*256 / 64

__device__ float g_R2[8 * 256 * 128];     // Vx + 0.5*Ub  (1 MB)
__device__ float4 g_Q01[4 * 16 * 32];     // streamed B pairs oc0,1 (32 KB)
__device__ float4 g_Q23[4 * 16 * 32];     // streamed B pairs oc2,3 (32 KB)

__device__ __forceinline__ uint32_t f2tf32(float f) {
    uint32_t r;
    asm("cvt.rna.tf32.f32 %0, %1;" : "=r"(r) : "f"(f));
    return r;
}
__device__ __forceinline__ uint32_t smem_u32(const void* p) {
    uint32_t a;
    asm("{ .reg .u64 t; cvta.to.shared.u64 t, %1; cvt.u32.u64 %0, t; }" : "=r"(a) : "l"(p));
    return a;
}

// Stage one 64x128 fp32 tile into SMEM via cp.async.cg; ALWAYS commits a group.
__device__ __forceinline__ void stage_cp(uint32_t sdst, const float* __restrict__ src,
                                         int tid, bool pred) {
    if (pred) {
#pragma unroll
        for (int q = 0; q < 8; q++) {
            int idx = tid + q * THREADS;                   // 0..2047 x 16B
            uint32_t dst = sdst + (uint32_t)((idx >> 5) * (STRIDE * 4) + (idx & 31) * 16);
            asm volatile("cp.async.cg.shared.global [%0], [%1], 16;"
                         :: "r"(dst), "l"(src + (size_t)idx * 4) : "memory");
        }
    }
    asm volatile("cp.async.commit_group;" ::: "memory");
}

// ---------------------------------------------------------------------------
// Fused prep kernel. Blocks [0,128): Vx (16 rows each — V_w read once per
// block, 8 MB total L2 traffic). Blocks [128,144): pack U_w.
// Pack permutation: o = nc*32 + 8*(g>>1) + 2*oc + (g&1); thread (g,tg) then
// owns o-range [nc*32 + 8*tg, +8) contiguously in the epilogue.
// ---------------------------------------------------------------------------
__global__ __launch_bounds__(256) void prep_kernel(
    const float* __restrict__ x,  const float* __restrict__ Vw,
    const float* __restrict__ Vb, const float* __restrict__ Ub,
    const float* __restrict__ Uw)
{
    if (blockIdx.x >= 128) {                     // ---- pack part ----
        int p = (blockIdx.x - 128) * 256 + threadIdx.x;   // 0..4095
        int r    = p & 2047;
        int lane = r & 31, ks = (r >> 5) & 15, nc = r >> 9;
        int g    = lane >> 2;
        int k0   = ks * 8 + (lane & 3);
        int base = nc * 32 + 8 * (g >> 1) + (g & 1);
        if (p < 2048) {                          // oc 0,1
            int row0 = base + 0, row1 = base + 2;
            g_Q01[r] = make_float4(
                __uint_as_float(f2tf32(Uw[row0 * 128 + k0])),
                __uint_as_float(f2tf32(Uw[row0 * 128 + k0 + 4])),
                __uint_as_float(f2tf32(Uw[row1 * 128 + k0])),
                __uint_as_float(f2tf32(Uw[row1 * 128 + k0 + 4])));
        } else {                                 // oc 2,3
            int row2 = base + 4, row3 = base + 6;
            g_Q23[r] = make_float4(
                __uint_as_float(f2tf32(Uw[row2 * 128 + k0])),
                __uint_as_float(f2tf32(Uw[row2 * 128 + k0 + 4])),
                __uint_as_float(f2tf32(Uw[row3 * 128 + k0])),
                __uint_as_float(f2tf32(Uw[row3 * 128 + k0 + 4])));
        }
        return;
    }
    // ---- Vx part: 16 rows per block ----
    __shared__ float xs[16 * 128];
    int tid = threadIdx.x;
    int rbase = blockIdx.x * 16;
    const float4* xp = reinterpret_cast<const float4*>(x + rbase * 128);
    float4* xsp = reinterpret_cast<float4*>(xs);
#pragma unroll
    for (int q = 0; q < 2; q++) xsp[tid + q * 256] = xp[tid + q * 256];
    __syncthreads();

    int o  = tid & 127;
    int r0 = tid >> 7;                           // 0/1; rows r0+2k, k<8
    float acc[8];
    float bias = Vb[o] + 0.5f * Ub[o];
#pragma unroll
    for (int k = 0; k < 8; k++) acc[k] = bias;
    const float4* wr = reinterpret_cast<const float4*>(Vw + o * 128);
#pragma unroll
    for (int h4 = 0; h4 < 32; h4++) {
        float4 w = wr[h4];
#pragma unroll
        for (int k = 0; k < 8; k++) {
            const float* xr = xs + (r0 + 2 * k) * 128 + h4 * 4;
            acc[k] += w.x * xr[0] + w.y * xr[1] + w.z * xr[2] + w.w * xr[3];
        }
    }
#pragma unroll
    for (int k = 0; k < 8; k++)
        g_R2[(rbase + r0 + 2 * k) * 128 + o] = acc[k];
}

// ---------------------------------------------------------------------------
// Edge kernel (round-16 winner; epilogue Rj loads batched for MLP).
// 256 threads, 8 warps = 2 row-groups x 4 n-chunks over a 64-row tile;
// all B streamed from L1-resident packed tables; manual ks pipeline.
//   out[m,o] = e[m,:].Uw[o,:] + R2[b,i,o] + R2[b,j,o]
// ---------------------------------------------------------------------------
__global__ __launch_bounds__(THREADS, 2) void edge_kernel(
    const float* __restrict__ e, float* __restrict__ out)
{
    extern __shared__ float smem[];
    const int tid  = threadIdx.x;
    const int lane = tid & 31;
    const int warp = tid >> 5;
    const int rg   = warp >> 2;              // row group 0/1
    const int nc   = warp & 3;               // n chunk
    const int g    = lane >> 2;
    const int tg   = lane & 3;
    const int ob8  = nc * 32 + 8 * tg;       // thread's contiguous o-range start
    uint32_t sbase = smem_u32(smem);

    // ldmatrix per-lane byte offset within the warp's 32-row group
    const uint32_t lmoff = (uint32_t)(
        (rg * 32 + (((lane >> 3) & 1) * 8 + (lane & 7))) * STRIDE * 4
        + (lane >> 4) * 16);

    const float4* Q01p = g_Q01 + (size_t)(nc * 16) * 32 + lane;
    const float4* Q23p = g_Q23 + (size_t)(nc * 16) * 32 + lane;

    const int G  = (int)gridDim.x;
    const int t0 = (int)blockIdx.x;
    stage_cp(sbase, e + (size_t)t0 * (TILE_ROWS * 128), tid, t0 < NTILES);

    int s = 0;
    for (int t = t0; t < NTILES; t += G, s++) {
        const int buf = s & 1;
        const int base_m = t * TILE_ROWS;
        const int b  = base_m >> 16;
        const int i  = (base_m >> 8) & 255;
        const int j0 = base_m & 255;

        // ---- Prefetch row-bias Ri only (8 regs); Rj batched in epilogue ----
        float4 si0, si1;
        {
            const float* Ri = g_R2 + ((size_t)(b * 256 + i) * 128 + ob8);
            si0 = *reinterpret_cast<const float4*>(Ri);
            si1 = *reinterpret_cast<const float4*>(Ri + 4);
        }

        asm volatile("cp.async.wait_group 0;" ::: "memory");
        __syncthreads();                         // tile buf ready; buf^1 free
        {
            const int tn = t + G;
            stage_cp(sbase + (uint32_t)((buf ^ 1) * TILE_SMEM_BYTES),
                     e + (size_t)tn * (TILE_ROWS * 128), tid, tn < NTILES);
        }

        const uint32_t abase = sbase + (uint32_t)(buf * TILE_SMEM_BYTES) + lmoff;
        float c[2][4][4];
#pragma unroll
        for (int mt = 0; mt < 2; mt++)
#pragma unroll
            for (int oc = 0; oc < 4; oc++)
#pragma unroll
                for (int q = 0; q < 4; q++) c[mt][oc][q] = 0.f;

        // ---- Manually double-buffered ks pipeline ----
        uint32_t A[2][2][4];      // [pipe buf][mt][frag]
        uint32_t Bq[2][8];        // [pipe buf][B0..B3 x2]
        {
            float4 b01 = Q01p[0], b23 = Q23p[0];
            Bq[0][0] = __float_as_uint(b01.x); Bq[0][1] = __float_as_uint(b01.y);
            Bq[0][2] = __float_as_uint(b01.z); Bq[0][3] = __float_as_uint(b01.w);
            Bq[0][4] = __float_as_uint(b23.x); Bq[0][5] = __float_as_uint(b23.y);
            Bq[0][6] = __float_as_uint(b23.z); Bq[0][7] = __float_as_uint(b23.w);
#pragma unroll
            for (int mt = 0; mt < 2; mt++)
                asm volatile(
                    "ldmatrix.sync.aligned.m8n8.x4.shared.b16 {%0,%1,%2,%3}, [%4];"
                    : "=r"(A[0][mt][0]), "=r"(A[0][mt][1]),
                      "=r"(A[0][mt][2]), "=r"(A[0][mt][3])
                    : "r"(abase + (uint32_t)(mt * 16 * STRIDE * 4)));
        }
#pragma unroll
        for (int ks = 0; ks < 16; ks++) {
            const int cur = ks & 1;
            if (ks < 15) {
                const int nxt = cur ^ 1;
                float4 b01 = Q01p[(ks + 1) * 32], b23 = Q23p[(ks + 1) * 32];
                Bq[nxt][0] = __float_as_uint(b01.x); Bq[nxt][1] = __float_as_uint(b01.y);
                Bq[nxt][2] = __float_as_uint(b01.z); Bq[nxt][3] = __float_as_uint(b01.w);
                Bq[nxt][4] = __float_as_uint(b23.x); Bq[nxt][5] = __float_as_uint(b23.y);
                Bq[nxt][6] = __float_as_uint(b23.z); Bq[nxt][7] = __float_as_uint(b23.w);
#pragma unroll
                for (int mt = 0; mt < 2; mt++)
                    asm volatile(
                        "ldmatrix.sync.aligned.m8n8.x4.shared.b16 {%0,%1,%2,%3}, [%4];"
                        : "=r"(A[nxt][mt][0]), "=r"(A[nxt][mt][1]),
                          "=r"(A[nxt][mt][2]), "=r"(A[nxt][mt][3])
                        : "r"(abase + (uint32_t)((mt * 16 * STRIDE + (ks + 1) * 8) * 4)));
            }
#pragma unroll
            for (int mt = 0; mt < 2; mt++) {
#pragma unroll
                for (int oc = 0; oc < 4; oc++)
                    asm volatile(
                        "mma.sync.aligned.m16n8k8.row.col.f32.tf32.tf32.f32 "
                        "{%0,%1,%2,%3}, {%4,%5,%6,%7}, {%8,%9}, {%0,%1,%2,%3};"
                        : "+f"(c[mt][oc][0]), "+f"(c[mt][oc][1]),
                          "+f"(c[mt][oc][2]), "+f"(c[mt][oc][3])
                        : "r"(A[cur][mt][0]), "r"(A[cur][mt][1]),
                          "r"(A[cur][mt][2]), "r"(A[cur][mt][3]),
                          "r"(Bq[cur][oc * 2]), "r"(Bq[cur][oc * 2 + 1]));
            }
        }

        // ---- Epilogue: batched Rj loads (MLP=8; reuses dead pipe regs) ----
        const float* Rbase = g_R2 + ((size_t)(b * 256 + j0) * 128 + ob8);
        float4 Rj[4][2];
#pragma unroll
        for (int q = 0; q < 4; q++) {
            const int row = rg * 32 + (q >> 1) * 16 + (q & 1) * 8 + g;
            Rj[q][0] = *reinterpret_cast<const float4*>(Rbase + (size_t)row * 128);
            Rj[q][1] = *reinterpret_cast<const float4*>(Rbase + (size_t)row * 128 + 4);
        }
#pragma unroll
        for (int q = 0; q < 4; q++) {
            const int mt = q >> 1;
            const int h2 = (q & 1) * 2;
            const int row = rg * 32 + (q >> 1) * 16 + (q & 1) * 8 + g;
            float4 v0 = make_float4(c[mt][0][h2]     + si0.x + Rj[q][0].x,
                                    c[mt][0][h2 + 1] + si0.y + Rj[q][0].y,
                                    c[mt][1][h2]     + si0.z + Rj[q][0].z,
                                    c[mt][1][h2 + 1] + si0.w + Rj[q][0].w);
            float4 v1 = make_float4(c[mt][2][h2]     + si1.x + Rj[q][1].x,
                                    c[mt][2][h2 + 1] + si1.y + Rj[q][1].y,
                                    c[mt][3][h2]     + si1.z + Rj[q][1].z,
                                    c[mt][3][h2 + 1] + si1.w + Rj[q][1].w);
            float* op = out + ((size_t)(base_m + row) * 128 + ob8);
            __stcs(reinterpret_cast<float4*>(op),     v0);
            __stcs(reinterpret_cast<float4*>(op + 4), v1);
        }
    }
}

// ---------------------------------------------------------------------------
// Inputs (metadata order): x, e, U_w, U_b, V_w, V_b. Output fp32 [8,256,256,128].
// ---------------------------------------------------------------------------
extern "C" void kernel_launch(void* const* d_in, const int* in_sizes, int n_in,
                              void* d_out, int out_size) {
    const float* x  = (const float*)d_in[0];
    const float* e  = (const float*)d_in[1];
    const float* Uw = (const float*)d_in[2];
    const float* Ub = (const float*)d_in[3];
    const float* Vw = (const float*)d_in[4];
    const float* Vb = (const float*)d_in[5];
    float* out = (float*)d_out;

    cudaFuncSetAttribute(edge_kernel, cudaFuncAttributeMaxDynamicSharedMemorySize,
                         NSTAGE * TILE_SMEM_BYTES);

    int nsm = 148;
    cudaDeviceGetAttribute(&nsm, cudaDevAttrMultiProcessorCount, 0);

    prep_kernel<<<144, 256>>>(x, Vw, Vb, Ub, Uw);
    edge_kernel<<<2 * nsm, THREADS, NSTAGE * TILE_SMEM_BYTES>>>(e, out);
}